// round 8
// baseline (speedup 1.0000x reference)
#include <cuda_runtime.h>
#include <cuda_bf16.h>
#include <math.h>

#define N_NODES 19
#define N_T     4096
#define LATENT  512
#define HID     2048
#define N_EDGES 342

// ---------------- scratch (__device__ globals; no allocs allowed) -----------
__device__ float g_accA[N_NODES * N_T];
__device__ float g_accB[N_NODES * N_T];
__device__ float g_accC[N_NODES * N_T];
__device__ float g_v[LATENT];
__device__ float g_adjf[N_NODES * N_NODES]; // dense edge-count matrix [dst][src]

// ---------------- K0: adjacency + zero all accumulators ---------------------
__global__ void init_kernel(const void* __restrict__ eidx,
                            float* __restrict__ accA,
                            float* __restrict__ accB,
                            float* __restrict__ accC,
                            float* __restrict__ v) {
    int t = threadIdx.x;
    if (blockIdx.x == 0) {
        __shared__ int cnt[N_NODES * N_NODES];
        __shared__ int s_i64;
        for (int i = t; i < N_NODES * N_NODES; i += blockDim.x) cnt[i] = 0;
        if (t == 0) {
            const long long* e64 = (const long long*)eidx;
            int ok = 1;
            for (int i = 0; i < N_EDGES; ++i) {
                long long x = e64[i];
                if (x < 0 || x >= N_NODES) { ok = 0; break; }
            }
            s_i64 = ok;
        }
        __syncthreads();
        const long long* e64 = (const long long*)eidx;
        const int*       e32 = (const int*)eidx;
        for (int e = t; e < N_EDGES; e += blockDim.x) {
            int src, dst;
            if (s_i64) { src = (int)e64[e]; dst = (int)e64[N_EDGES + e]; }
            else       { src = e32[e];      dst = e32[N_EDGES + e]; }
            atomicAdd(&cnt[dst * N_NODES + src], 1);
        }
        __syncthreads();
        for (int i = t; i < N_NODES * N_NODES; i += blockDim.x)
            g_adjf[i] = (float)cnt[i];
        for (int i = t; i < LATENT; i += blockDim.x) v[i] = 0.0f;
    }
    const int n4 = (N_NODES * N_T) >> 2;
    float4 zz = make_float4(0.f, 0.f, 0.f, 0.f);
    for (int q = blockIdx.x * blockDim.x + t; q < n4;
         q += gridDim.x * blockDim.x) {
        reinterpret_cast<float4*>(accA)[q] = zz;
        reinterpret_cast<float4*>(accB)[q] = zz;
        reinterpret_cast<float4*>(accC)[q] = zz;
    }
}

// ---------------- fused split-K GEMM with cp.async W pipeline ---------------
// Cacc += stage(Ain)[19, K] @ W[K, N].  256 threads x 2 cols = 512-col tile.
// W streamed via S-stage cp.async ring; A staged once as duplicated {a,a}
// pairs. Inner loop register-pipelines the A LDS stream (batches of 4,
// double-buffered) and hoists the next W LDS pair, so shared-memory latency
// (29 cyc) is covered by in-flight batches instead of being exposed per-r.
// MODE 0: stage = agg(Ain); 1: relu(Ain+bias); 2: agg(relu(Ain+bias)).
template<int KC, int MODE, int S>
__global__ __launch_bounds__(256, 2) void gemm_pipe(
        const float* __restrict__ Ain, const float* __restrict__ bias,
        const float* __restrict__ W, float* __restrict__ Cacc,
        float* __restrict__ zbuf, int zn, int K, int N) {
    extern __shared__ __align__(16) char dsm[];
    float* sW = (float*)dsm;                                    // S*8*512 floats
    unsigned long long* sA =
        (unsigned long long*)(dsm + (size_t)S * 8 * 512 * 4);   // [19][KC]
    float* sRaw = (float*)(sA + N_NODES * KC);                  // [19][KC] (MODE!=1)
    __shared__ float s_adj[N_NODES * N_NODES];

    const int tid = threadIdx.x;
    const int colbase = blockIdx.x * 512;
    const int kbeg = blockIdx.y * KC;

    // lazy zeroing for a future accumulator
    if (zbuf) {
        int n4 = zn >> 2;
        float4 zz = make_float4(0.f, 0.f, 0.f, 0.f);
        for (int q = (blockIdx.y * gridDim.x + blockIdx.x) * 256 + tid;
             q < n4; q += gridDim.x * gridDim.y * 256)
            reinterpret_cast<float4*>(zbuf)[q] = zz;
    }
    if (MODE != 1) {
        for (int i = tid; i < N_NODES * N_NODES; i += 256)
            s_adj[i] = g_adjf[i];
    }

    // ---- stage A slab (fused epilogue/agg), duplicated pairs ----
    for (int i = tid; i < N_NODES * KC; i += 256) {
        int r = i / KC, k = i - r * KC;
        float a = Ain[r * K + kbeg + k];
        if (MODE >= 1) a = fmaxf(a + bias[kbeg + k], 0.0f);
        if (MODE == 1) {
            unsigned long long p;
            asm("mov.b64 %0, {%1, %1};" : "=l"(p) : "f"(a));
            sA[i] = p;
        } else {
            sRaw[i] = a;
        }
    }
    __syncthreads();
    if (MODE != 1) {
        for (int i = tid; i < N_NODES * KC; i += 256) {
            int r = i / KC, k = i - r * KC;
            float a = sRaw[r * KC + k];
#pragma unroll
            for (int s = 0; s < N_NODES; ++s)
                a += s_adj[r * N_NODES + s] * sRaw[s * KC + k];
            unsigned long long p;
            asm("mov.b64 %0, {%1, %1};" : "=l"(p) : "f"(a));
            sA[i] = p;
        }
        __syncthreads();
    }

    constexpr int NST = KC / 8;   // 8-k stages in this slab

    // issue one stage's cp.async loads (16 KB; 4 x 16B per thread)
    auto issue_stage = [&](int s) {
        const float* gsrc = W + (size_t)(kbeg + s * 8) * N + colbase;
        float* dst = sW + (s % S) * 4096;
#pragma unroll
        for (int j = 0; j < 4; ++j) {
            int id  = tid + j * 256;          // 0..1023
            int row = id >> 7;                // 8 rows
            int cp  = (id & 127) << 2;        // 128 x 4-col chunks
            unsigned sm =
                (unsigned)__cvta_generic_to_shared(dst + row * 512 + cp);
            const float* g = gsrc + (size_t)row * N + cp;
            asm volatile("cp.async.cg.shared.global [%0], [%1], 16;\n"
                         :: "r"(sm), "l"(g));
        }
    };

    unsigned long long acc[N_NODES];
#pragma unroll
    for (int r = 0; r < N_NODES; ++r) acc[r] = 0ull;

    // prologue: fill S-1 stages
#pragma unroll
    for (int s = 0; s < S - 1; ++s) {
        if (s < NST) issue_stage(s);
        asm volatile("cp.async.commit_group;\n");
    }

#pragma unroll 1
    for (int st = 0; st < NST; ++st) {
        asm volatile("cp.async.wait_group %0;\n" :: "n"(S - 2));
        __syncthreads();   // stage st data arrived; buffer (st-1)%S free

        const float* wb = sW + (st % S) * 4096;
        unsigned long long w0 =
            *reinterpret_cast<const unsigned long long*>(wb + 2 * tid);
        unsigned long long w1 =
            *reinterpret_cast<const unsigned long long*>(wb + 512 + 2 * tid);

#pragma unroll
        for (int kk = 0; kk < 8; kk += 2) {
            // hoist next kk's W pair (consumed ~40 instrs later)
            unsigned long long nw0 = 0, nw1 = 0;
            if (kk < 6) {
                nw0 = *reinterpret_cast<const unsigned long long*>(
                          wb + (kk + 2) * 512 + 2 * tid);
                nw1 = *reinterpret_cast<const unsigned long long*>(
                          wb + (kk + 3) * 512 + 2 * tid);
            }
            const int koff = st * 8 + kk;
            // register double-buffered A batches of 4 rows
            ulonglong2 cur[4], nxt[4];
#pragma unroll
            for (int j = 0; j < 4; ++j)
                cur[j] = *reinterpret_cast<const ulonglong2*>(
                             sA + j * KC + koff);
#pragma unroll
            for (int b = 0; b < 5; ++b) {
                const int base = b * 4;
#pragma unroll
                for (int j = 0; j < 4; ++j) {
                    const int nr = base + 4 + j;
                    nxt[j] = (nr < N_NODES)
                                 ? *reinterpret_cast<const ulonglong2*>(
                                       sA + nr * KC + koff)
                                 : cur[j];
                }
#pragma unroll
                for (int j = 0; j < 4; ++j) {
                    const int r = base + j;
                    if (r < N_NODES) {
                        asm("fma.rn.f32x2 %0, %1, %2, %0;"
                            : "+l"(acc[r]) : "l"(cur[j].x), "l"(w0));
                        asm("fma.rn.f32x2 %0, %1, %2, %0;"
                            : "+l"(acc[r]) : "l"(cur[j].y), "l"(w1));
                    }
                }
#pragma unroll
                for (int j = 0; j < 4; ++j) cur[j] = nxt[j];
            }
            w0 = nw0; w1 = nw1;
        }
        if (st + S - 1 < NST) issue_stage(st + S - 1);
        asm volatile("cp.async.commit_group;\n");
    }

    const int col = colbase + tid * 2;
#pragma unroll
    for (int r = 0; r < N_NODES; ++r) {
        float2 p = *reinterpret_cast<float2*>(&acc[r]);
        atomicAdd(&Cacc[r * N + col],     p.x);
        atomicAdd(&Cacc[r * N + col + 1], p.y);
    }
}

// ---------------- FC1 fused: flat = acc + b2b (also written to out1);
//                  v[512] += flat @ Wc1 --------------------------------------
__global__ __launch_bounds__(128) void fc1_kernel(
        const float* __restrict__ acc, const float* __restrict__ b2b,
        const float* __restrict__ Wc1, float* __restrict__ v,
        float* __restrict__ out1, int rows_per) {
    const int ROWS = N_NODES * N_T;
    int t = threadIdx.x;                       // cols 4t..4t+3
    int r0 = blockIdx.x * rows_per;
    int r1 = min(r0 + rows_per, ROWS);
    float4 s = make_float4(0.f, 0.f, 0.f, 0.f);
    int i = r0;
    for (; i + 8 <= r1; i += 8) {
        float f[8];
        float4 w[8];
#pragma unroll
        for (int u = 0; u < 8; ++u) {
            f[u] = acc[i + u] + b2b[(i + u) & (N_T - 1)];
            w[u] = *reinterpret_cast<const float4*>(
                       &Wc1[(size_t)(i + u) * LATENT + 4 * t]);
        }
#pragma unroll
        for (int u = 0; u < 8; ++u) {
            if (t == ((i + u) & 127)) out1[i + u] = f[u];
            s.x += f[u] * w[u].x; s.y += f[u] * w[u].y;
            s.z += f[u] * w[u].z; s.w += f[u] * w[u].w;
        }
    }
    for (; i < r1; ++i) {
        float f = acc[i] + b2b[i & (N_T - 1)];
        if (t == (i & 127)) out1[i] = f;
        float4 w = *reinterpret_cast<const float4*>(
                       &Wc1[(size_t)i * LATENT + 4 * t]);
        s.x += f * w.x; s.y += f * w.y; s.z += f * w.z; s.w += f * w.w;
    }
    atomicAdd(&v[4 * t],     s.x);
    atomicAdd(&v[4 * t + 1], s.y);
    atomicAdd(&v[4 * t + 2], s.z);
    atomicAdd(&v[4 * t + 3], s.w);
}

// ---------------- FC2 + sigmoid ---------------------------------------------
__global__ void fc2_kernel(const float* __restrict__ v,
                           const float* __restrict__ bc1,
                           const float* __restrict__ Wc2,
                           const float* __restrict__ bc2,
                           float* __restrict__ out) {
    __shared__ float red[LATENT];
    int j = threadIdx.x;
    red[j] = (v[j] + bc1[j]) * Wc2[j];
    __syncthreads();
    for (int s = LATENT / 2; s > 0; s >>= 1) {
        if (j < s) red[j] += red[j + s];
        __syncthreads();
    }
    if (j == 0) out[0] = 1.0f / (1.0f + expf(-(red[0] + bc2[0])));
}

// ---------------- launch ----------------------------------------------------
#define PIPE_S 5
static inline int pipe_smem(int kc, int mode) {
    return PIPE_S * 8 * 512 * 4 + kc * N_NODES * 8 +
           (mode != 1 ? kc * N_NODES * 4 : 0);
}

extern "C" void kernel_launch(void* const* d_in, const int* in_sizes, int n_in,
                              void* d_out, int out_size) {
    const float* z    = (const float*)d_in[0];
    const void*  eidx = d_in[1];
    const float* W1a  = (const float*)d_in[2];
    const float* b1a  = (const float*)d_in[3];
    const float* W1b  = (const float*)d_in[4];
    const float* b1b  = (const float*)d_in[5];
    const float* W2a  = (const float*)d_in[6];
    const float* b2a  = (const float*)d_in[7];
    const float* W2b  = (const float*)d_in[8];
    const float* b2b  = (const float*)d_in[9];
    const float* Wc1  = (const float*)d_in[10];
    const float* bc1  = (const float*)d_in[11];
    const float* Wc2  = (const float*)d_in[12];
    const float* bc2  = (const float*)d_in[13];
    float* out = (float*)d_out;

    float *accA, *accB, *accC, *v;
    cudaGetSymbolAddress((void**)&accA, g_accA);
    cudaGetSymbolAddress((void**)&accB, g_accB);
    cudaGetSymbolAddress((void**)&accC, g_accC);
    cudaGetSymbolAddress((void**)&v,    g_v);

    const int nNT = N_NODES * N_T;   // 77824

    // opt-in to >48KB dynamic smem (idempotent; host-state only)
    static int attr_done = 0;
    if (!attr_done) {
        cudaFuncSetAttribute(gemm_pipe<32, 0, PIPE_S>,
            cudaFuncAttributeMaxDynamicSharedMemorySize, pipe_smem(32, 0));
        cudaFuncSetAttribute(gemm_pipe<64, 1, PIPE_S>,
            cudaFuncAttributeMaxDynamicSharedMemorySize, pipe_smem(64, 1));
        cudaFuncSetAttribute(gemm_pipe<64, 2, PIPE_S>,
            cudaFuncAttributeMaxDynamicSharedMemorySize, pipe_smem(64, 2));
        cudaFuncSetAttribute(gemm_pipe<128, 1, PIPE_S>,
            cudaFuncAttributeMaxDynamicSharedMemorySize, pipe_smem(128, 1));
        attr_done = 1;
    }

    // K0: adjacency + zero accA/accB/accC/v
    init_kernel<<<148, 256>>>(eidx, accA, accB, accC, v);

    // g1a: accA = agg(z) @ W1a          [19,512]x[512,2048]
    gemm_pipe<32, 0, PIPE_S><<<dim3(HID / 512, LATENT / 32), 256,
                               pipe_smem(32, 0)>>>(
        z, nullptr, W1a, accA, nullptr, 0, LATENT, HID);

    // g1b: accB = relu(accA+b1a) @ W1b  [19,2048]x[2048,2048]
    gemm_pipe<64, 1, PIPE_S><<<dim3(HID / 512, HID / 64), 256,
                               pipe_smem(64, 1)>>>(
        accA, b1a, W1b, accB, nullptr, 0, HID, HID);

    // g2a: accC = agg(relu(accB+b1b)) @ W2a  [19,2048]x[2048,4096]
    //      (also lazily zeroes accA for g2b)
    gemm_pipe<64, 2, PIPE_S><<<dim3(N_T / 512, HID / 64), 256,
                               pipe_smem(64, 2)>>>(
        accB, b1b, W2a, accC, accA, nNT, HID, N_T);

    // g2b: accA = relu(accC+b2a) @ W2b  [19,4096]x[4096,4096]
    gemm_pipe<128, 1, PIPE_S><<<dim3(N_T / 512, N_T / 128), 256,
                                pipe_smem(128, 1)>>>(
        accC, b2a, W2b, accA, nullptr, 0, N_T, N_T);

    // classifier: epilogue (+b2b, write out[1:]) fused into FC1
    fc1_kernel<<<592, 128>>>(accA, b2b, Wc1, v, out + 1, 132);
    fc2_kernel<<<1, 512>>>(v, bc1, Wc2, bc2, out);
}

// round 9
// speedup vs baseline: 1.2360x; 1.2360x over previous
#include <cuda_runtime.h>
#include <cuda_bf16.h>
#include <math.h>

#define N_NODES 19
#define N_T     4096
#define LATENT  512
#define HID     2048
#define N_EDGES 342

// ---------------- scratch (__device__ globals; no allocs allowed) -----------
__device__ __align__(16) float g_accA[N_NODES * N_T];
__device__ __align__(16) float g_accB[N_NODES * N_T];
__device__ __align__(16) float g_accC[N_NODES * N_T];
__device__ __align__(16) float g_v[LATENT];
__device__ float g_adjf[N_NODES * N_NODES]; // dense edge-count matrix [dst][src]

// ---------------- K0: adjacency + zero all accumulators ---------------------
__global__ void init_kernel(const void* __restrict__ eidx,
                            float* __restrict__ accA,
                            float* __restrict__ accB,
                            float* __restrict__ accC,
                            float* __restrict__ v) {
    int t = threadIdx.x;
    if (blockIdx.x == 0) {
        __shared__ int cnt[N_NODES * N_NODES];
        __shared__ int s_i64;
        for (int i = t; i < N_NODES * N_NODES; i += blockDim.x) cnt[i] = 0;
        if (t == 0) {
            const long long* e64 = (const long long*)eidx;
            int ok = 1;
            for (int i = 0; i < N_EDGES; ++i) {
                long long x = e64[i];
                if (x < 0 || x >= N_NODES) { ok = 0; break; }
            }
            s_i64 = ok;
        }
        __syncthreads();
        const long long* e64 = (const long long*)eidx;
        const int*       e32 = (const int*)eidx;
        for (int e = t; e < N_EDGES; e += blockDim.x) {
            int src, dst;
            if (s_i64) { src = (int)e64[e]; dst = (int)e64[N_EDGES + e]; }
            else       { src = e32[e];      dst = e32[N_EDGES + e]; }
            atomicAdd(&cnt[dst * N_NODES + src], 1);
        }
        __syncthreads();
        for (int i = t; i < N_NODES * N_NODES; i += blockDim.x)
            g_adjf[i] = (float)cnt[i];
        for (int i = t; i < LATENT; i += blockDim.x) v[i] = 0.0f;
    }
    const int n4 = (N_NODES * N_T) >> 2;
    float4 zz = make_float4(0.f, 0.f, 0.f, 0.f);
    for (int q = blockIdx.x * blockDim.x + t; q < n4;
         q += gridDim.x * blockDim.x) {
        reinterpret_cast<float4*>(accA)[q] = zz;
        reinterpret_cast<float4*>(accB)[q] = zz;
        reinterpret_cast<float4*>(accC)[q] = zz;
    }
}

// ---------------- fused split-K GEMM, 4 cols/thread, v4 atomic epilogue -----
// Cacc += stage(Ain)[19, K] @ W[K, N].  128 threads x 4 cols = 512-col tile.
// W streamed via S-stage cp.async ring (stage = 8 k-rows x 512 cols = 16 KB).
// A staged once per slab as duplicated {a,a} pairs (fused agg/bias/relu).
// Epilogue: ONE red.global.add.v4.f32 per row (4x fewer atomic lane-ops than
// scalar atomicAdd) -- the split-K reduction floor identified in R8.
// MODE 0: stage = agg(Ain); 1: relu(Ain+bias); 2: agg(relu(Ain+bias)).
template<int KC, int MODE, int S>
__global__ __launch_bounds__(128) void gemm_pipe(
        const float* __restrict__ Ain, const float* __restrict__ bias,
        const float* __restrict__ W, float* __restrict__ Cacc,
        float* __restrict__ zbuf, int zn, int K, int N) {
    extern __shared__ __align__(16) char dsm[];
    float* sW = (float*)dsm;                                    // S*8*512 floats
    unsigned long long* sA =
        (unsigned long long*)(dsm + (size_t)S * 8 * 512 * 4);   // [19][KC]
    float* sRaw = (float*)(sA + N_NODES * KC);                  // [19][KC] (MODE!=1)
    __shared__ float s_adj[N_NODES * N_NODES];

    const int tid = threadIdx.x;
    const int colbase = blockIdx.x * 512;
    const int kbeg = blockIdx.y * KC;

    // lazy zeroing for a future accumulator
    if (zbuf) {
        int n4 = zn >> 2;
        float4 zz = make_float4(0.f, 0.f, 0.f, 0.f);
        for (int q = (blockIdx.y * gridDim.x + blockIdx.x) * 128 + tid;
             q < n4; q += gridDim.x * gridDim.y * 128)
            reinterpret_cast<float4*>(zbuf)[q] = zz;
    }
    if (MODE != 1) {
        for (int i = tid; i < N_NODES * N_NODES; i += 128)
            s_adj[i] = g_adjf[i];
    }

    // ---- stage A slab (fused epilogue/agg), duplicated pairs ----
    for (int i = tid; i < N_NODES * KC; i += 128) {
        int r = i / KC, k = i - r * KC;
        float a = Ain[r * K + kbeg + k];
        if (MODE >= 1) a = fmaxf(a + bias[kbeg + k], 0.0f);
        if (MODE == 1) {
            unsigned long long p;
            asm("mov.b64 %0, {%1, %1};" : "=l"(p) : "f"(a));
            sA[i] = p;
        } else {
            sRaw[i] = a;
        }
    }
    __syncthreads();
    if (MODE != 1) {
        for (int i = tid; i < N_NODES * KC; i += 128) {
            int r = i / KC, k = i - r * KC;
            float a = sRaw[r * KC + k];
#pragma unroll
            for (int s = 0; s < N_NODES; ++s)
                a += s_adj[r * N_NODES + s] * sRaw[s * KC + k];
            unsigned long long p;
            asm("mov.b64 %0, {%1, %1};" : "=l"(p) : "f"(a));
            sA[i] = p;
        }
        __syncthreads();
    }

    constexpr int NST = KC / 8;   // 8-k stages in this slab

    // issue one stage's cp.async loads (16 KB; 8 x 16B per thread)
    auto issue_stage = [&](int s) {
        const float* gsrc = W + (size_t)(kbeg + s * 8) * N + colbase;
        float* dst = sW + (s % S) * 4096;
#pragma unroll
        for (int j = 0; j < 8; ++j) {
            int id  = tid + j * 128;          // 0..1023
            int row = id >> 7;                // 8 rows
            int cp  = (id & 127) << 2;        // 128 x 4-col chunks
            unsigned sm =
                (unsigned)__cvta_generic_to_shared(dst + row * 512 + cp);
            const float* g = gsrc + (size_t)row * N + cp;
            asm volatile("cp.async.cg.shared.global [%0], [%1], 16;\n"
                         :: "r"(sm), "l"(g));
        }
    };

    // acc0[r] = cols {0,1}, acc1[r] = cols {2,3} (packed f32x2)
    unsigned long long acc0[N_NODES], acc1[N_NODES];
#pragma unroll
    for (int r = 0; r < N_NODES; ++r) { acc0[r] = 0ull; acc1[r] = 0ull; }

    // prologue: fill S-1 stages
#pragma unroll
    for (int s = 0; s < S - 1; ++s) {
        if (s < NST) issue_stage(s);
        asm volatile("cp.async.commit_group;\n");
    }

#pragma unroll 1
    for (int st = 0; st < NST; ++st) {
        asm volatile("cp.async.wait_group %0;\n" :: "n"(S - 2));
        __syncthreads();   // stage st data arrived; oldest buffer free

        const float* wb = sW + (st % S) * 4096;
        // W for this thread's 4 cols, k and k+1 (2 x LDS.128)
        ulonglong2 wv0 = *reinterpret_cast<const ulonglong2*>(wb + 4 * tid);
        ulonglong2 wv1 = *reinterpret_cast<const ulonglong2*>(wb + 512 + 4 * tid);

#pragma unroll
        for (int kk = 0; kk < 8; kk += 2) {
            ulonglong2 nwv0 = wv0, nwv1 = wv1;
            if (kk < 6) {   // hoist next k-pair's W
                nwv0 = *reinterpret_cast<const ulonglong2*>(
                           wb + (kk + 2) * 512 + 4 * tid);
                nwv1 = *reinterpret_cast<const ulonglong2*>(
                           wb + (kk + 3) * 512 + 4 * tid);
            }
            const int koff = st * 8 + kk;
            // register double-buffered A batches of 4 rows ({a,a} pairs, 2k)
            ulonglong2 cur[4], nxt[4];
#pragma unroll
            for (int j = 0; j < 4; ++j)
                cur[j] = *reinterpret_cast<const ulonglong2*>(
                             sA + j * KC + koff);
#pragma unroll
            for (int b = 0; b < 5; ++b) {
                const int base = b * 4;
#pragma unroll
                for (int j = 0; j < 4; ++j) {
                    const int nr = base + 4 + j;
                    nxt[j] = (nr < N_NODES)
                                 ? *reinterpret_cast<const ulonglong2*>(
                                       sA + nr * KC + koff)
                                 : cur[j];
                }
#pragma unroll
                for (int j = 0; j < 4; ++j) {
                    const int r = base + j;
                    if (r < N_NODES) {
                        asm("fma.rn.f32x2 %0, %1, %2, %0;"
                            : "+l"(acc0[r]) : "l"(cur[j].x), "l"(wv0.x));
                        asm("fma.rn.f32x2 %0, %1, %2, %0;"
                            : "+l"(acc1[r]) : "l"(cur[j].x), "l"(wv0.y));
                        asm("fma.rn.f32x2 %0, %1, %2, %0;"
                            : "+l"(acc0[r]) : "l"(cur[j].y), "l"(wv1.x));
                        asm("fma.rn.f32x2 %0, %1, %2, %0;"
                            : "+l"(acc1[r]) : "l"(cur[j].y), "l"(wv1.y));
                    }
                }
#pragma unroll
                for (int j = 0; j < 4; ++j) cur[j] = nxt[j];
            }
            wv0 = nwv0; wv1 = nwv1;
        }
        if (st + S - 1 < NST) issue_stage(st + S - 1);
        asm volatile("cp.async.commit_group;\n");
    }

    // ---- epilogue: one 128-bit reduction per row ----
    const int col = colbase + tid * 4;
#pragma unroll
    for (int r = 0; r < N_NODES; ++r) {
        float2 a01 = *reinterpret_cast<float2*>(&acc0[r]);
        float2 a23 = *reinterpret_cast<float2*>(&acc1[r]);
        asm volatile("red.global.add.v4.f32 [%0], {%1, %2, %3, %4};"
                     :: "l"(Cacc + r * N + col),
                        "f"(a01.x), "f"(a01.y), "f"(a23.x), "f"(a23.y)
                     : "memory");
    }
}

// ---------------- FC1 fused: flat = acc + b2b (also written to out1);
//                  v[512] += flat @ Wc1 --------------------------------------
__global__ __launch_bounds__(128) void fc1_kernel(
        const float* __restrict__ acc, const float* __restrict__ b2b,
        const float* __restrict__ Wc1, float* __restrict__ v,
        float* __restrict__ out1, int rows_per) {
    const int ROWS = N_NODES * N_T;
    int t = threadIdx.x;                       // cols 4t..4t+3
    int r0 = blockIdx.x * rows_per;
    int r1 = min(r0 + rows_per, ROWS);
    float4 s = make_float4(0.f, 0.f, 0.f, 0.f);
    int i = r0;
    for (; i + 8 <= r1; i += 8) {
        float f[8];
        float4 w[8];
#pragma unroll
        for (int u = 0; u < 8; ++u) {
            f[u] = acc[i + u] + b2b[(i + u) & (N_T - 1)];
            w[u] = *reinterpret_cast<const float4*>(
                       &Wc1[(size_t)(i + u) * LATENT + 4 * t]);
        }
#pragma unroll
        for (int u = 0; u < 8; ++u) {
            if (t == ((i + u) & 127)) out1[i + u] = f[u];
            s.x += f[u] * w[u].x; s.y += f[u] * w[u].y;
            s.z += f[u] * w[u].z; s.w += f[u] * w[u].w;
        }
    }
    for (; i < r1; ++i) {
        float f = acc[i] + b2b[i & (N_T - 1)];
        if (t == (i & 127)) out1[i] = f;
        float4 w = *reinterpret_cast<const float4*>(
                       &Wc1[(size_t)i * LATENT + 4 * t]);
        s.x += f * w.x; s.y += f * w.y; s.z += f * w.z; s.w += f * w.w;
    }
    asm volatile("red.global.add.v4.f32 [%0], {%1, %2, %3, %4};"
                 :: "l"(v + 4 * t), "f"(s.x), "f"(s.y), "f"(s.z), "f"(s.w)
                 : "memory");
}

// ---------------- FC2 + sigmoid ---------------------------------------------
__global__ void fc2_kernel(const float* __restrict__ v,
                           const float* __restrict__ bc1,
                           const float* __restrict__ Wc2,
                           const float* __restrict__ bc2,
                           float* __restrict__ out) {
    __shared__ float red[LATENT];
    int j = threadIdx.x;
    red[j] = (v[j] + bc1[j]) * Wc2[j];
    __syncthreads();
    for (int s = LATENT / 2; s > 0; s >>= 1) {
        if (j < s) red[j] += red[j + s];
        __syncthreads();
    }
    if (j == 0) out[0] = 1.0f / (1.0f + expf(-(red[0] + bc2[0])));
}

// ---------------- launch ----------------------------------------------------
#define PIPE_S 3
static inline int pipe_smem(int kc, int mode) {
    return PIPE_S * 8 * 512 * 4 + kc * N_NODES * 8 +
           (mode != 1 ? kc * N_NODES * 4 : 0);
}

extern "C" void kernel_launch(void* const* d_in, const int* in_sizes, int n_in,
                              void* d_out, int out_size) {
    const float* z    = (const float*)d_in[0];
    const void*  eidx = d_in[1];
    const float* W1a  = (const float*)d_in[2];
    const float* b1a  = (const float*)d_in[3];
    const float* W1b  = (const float*)d_in[4];
    const float* b1b  = (const float*)d_in[5];
    const float* W2a  = (const float*)d_in[6];
    const float* b2a  = (const float*)d_in[7];
    const float* W2b  = (const float*)d_in[8];
    const float* b2b  = (const float*)d_in[9];
    const float* Wc1  = (const float*)d_in[10];
    const float* bc1  = (const float*)d_in[11];
    const float* Wc2  = (const float*)d_in[12];
    const float* bc2  = (const float*)d_in[13];
    float* out = (float*)d_out;

    float *accA, *accB, *accC, *v;
    cudaGetSymbolAddress((void**)&accA, g_accA);
    cudaGetSymbolAddress((void**)&accB, g_accB);
    cudaGetSymbolAddress((void**)&accC, g_accC);
    cudaGetSymbolAddress((void**)&v,    g_v);

    const int nNT = N_NODES * N_T;   // 77824

    // opt-in to >48KB dynamic smem (idempotent; host-state only)
    static int attr_done = 0;
    if (!attr_done) {
        cudaFuncSetAttribute(gemm_pipe<32, 0, PIPE_S>,
            cudaFuncAttributeMaxDynamicSharedMemorySize, pipe_smem(32, 0));
        cudaFuncSetAttribute(gemm_pipe<32, 1, PIPE_S>,
            cudaFuncAttributeMaxDynamicSharedMemorySize, pipe_smem(32, 1));
        cudaFuncSetAttribute(gemm_pipe<64, 2, PIPE_S>,
            cudaFuncAttributeMaxDynamicSharedMemorySize, pipe_smem(64, 2));
        cudaFuncSetAttribute(gemm_pipe<128, 1, PIPE_S>,
            cudaFuncAttributeMaxDynamicSharedMemorySize, pipe_smem(128, 1));
        attr_done = 1;
    }

    // K0: adjacency + zero accA/accB/accC/v
    init_kernel<<<148, 256>>>(eidx, accA, accB, accC, v);

    // g1a: accA = agg(z) @ W1a          [19,512]x[512,2048]   64 blocks
    gemm_pipe<32, 0, PIPE_S><<<dim3(HID / 512, LATENT / 32), 128,
                               pipe_smem(32, 0)>>>(
        z, nullptr, W1a, accA, nullptr, 0, LATENT, HID);

    // g1b: accB = relu(accA+b1a) @ W1b  [19,2048]x[2048,2048] 256 blocks
    gemm_pipe<32, 1, PIPE_S><<<dim3(HID / 512, HID / 32), 128,
                               pipe_smem(32, 1)>>>(
        accA, b1a, W1b, accB, nullptr, 0, HID, HID);

    // g2a: accC = agg(relu(accB+b1b)) @ W2a  [19,2048]x[2048,4096] 256 blocks
    //      (also lazily zeroes accA for g2b)
    gemm_pipe<64, 2, PIPE_S><<<dim3(N_T / 512, HID / 64), 128,
                               pipe_smem(64, 2)>>>(
        accB, b1b, W2a, accC, accA, nNT, HID, N_T);

    // g2b: accA = relu(accC+b2a) @ W2b  [19,4096]x[4096,4096] 256 blocks
    gemm_pipe<128, 1, PIPE_S><<<dim3(N_T / 512, N_T / 128), 128,
                                pipe_smem(128, 1)>>>(
        accC, b2a, W2b, accA, nullptr, 0, N_T, N_T);

    // classifier: epilogue (+b2b, write out[1:]) fused into FC1
    fc1_kernel<<<592, 128>>>(accA, b2b, Wc1, v, out + 1, 132);
    fc2_kernel<<<1, 512>>>(v, bc1, Wc2, bc2, out);
}

// round 10
// speedup vs baseline: 1.2373x; 1.0011x over previous
#include <cuda_runtime.h>
#include <cuda_bf16.h>
#include <math.h>

#define N_NODES 19
#define N_T     4096
#define LATENT  512
#define HID     2048
#define N_EDGES 342

// ---------------- scratch (__device__ globals; no allocs allowed) -----------
__device__ __align__(16) float g_accA[N_NODES * N_T];
__device__ __align__(16) float g_accB[N_NODES * N_T];
__device__ __align__(16) float g_accC[N_NODES * N_T];
__device__ __align__(16) float g_v[LATENT];
__device__ float g_adjf[N_NODES * N_NODES]; // dense edge-count matrix [dst][src]

// ---------------- K0: adjacency + zero all accumulators ---------------------
__global__ void init_kernel(const void* __restrict__ eidx,
                            float* __restrict__ accA,
                            float* __restrict__ accB,
                            float* __restrict__ accC,
                            float* __restrict__ v) {
    int t = threadIdx.x;
    if (blockIdx.x == 0) {
        __shared__ int cnt[N_NODES * N_NODES];
        __shared__ int s_i64;
        for (int i = t; i < N_NODES * N_NODES; i += blockDim.x) cnt[i] = 0;
        if (t == 0) {
            const long long* e64 = (const long long*)eidx;
            int ok = 1;
            for (int i = 0; i < N_EDGES; ++i) {
                long long x = e64[i];
                if (x < 0 || x >= N_NODES) { ok = 0; break; }
            }
            s_i64 = ok;
        }
        __syncthreads();
        const long long* e64 = (const long long*)eidx;
        const int*       e32 = (const int*)eidx;
        for (int e = t; e < N_EDGES; e += blockDim.x) {
            int src, dst;
            if (s_i64) { src = (int)e64[e]; dst = (int)e64[N_EDGES + e]; }
            else       { src = e32[e];      dst = e32[N_EDGES + e]; }
            atomicAdd(&cnt[dst * N_NODES + src], 1);
        }
        __syncthreads();
        for (int i = t; i < N_NODES * N_NODES; i += blockDim.x)
            g_adjf[i] = (float)cnt[i];
        for (int i = t; i < LATENT; i += blockDim.x) v[i] = 0.0f;
    }
    const int n4 = (N_NODES * N_T) >> 2;
    float4 zz = make_float4(0.f, 0.f, 0.f, 0.f);
    for (int q = blockIdx.x * blockDim.x + t; q < n4;
         q += gridDim.x * blockDim.x) {
        reinterpret_cast<float4*>(accA)[q] = zz;
        reinterpret_cast<float4*>(accB)[q] = zz;
        reinterpret_cast<float4*>(accC)[q] = zz;
    }
}

// ---------------- fused split-K GEMM, 4 cols/thread, v4 atomic epilogue -----
// Cacc += stage(Ain)[19, K] @ W[K, N].  128 threads x 4 cols = 512-col tile.
// W streamed via S-stage cp.async ring (stage = 8 k-rows x 512 cols = 16 KB);
// next stage's loads are issued IMMEDIATELY after the barrier (before compute)
// for maximum latency cover. Epilogue: one red.global.add.v4.f32 per row.
// MODE 0: stage = agg(Ain); 1: relu(Ain+bias); 2: agg(relu(Ain+bias)).
template<int KC, int MODE, int S>
__global__ __launch_bounds__(128) void gemm_pipe(
        const float* __restrict__ Ain, const float* __restrict__ bias,
        const float* __restrict__ W, float* __restrict__ Cacc,
        float* __restrict__ zbuf, int zn, int K, int N) {
    extern __shared__ __align__(16) char dsm[];
    float* sW = (float*)dsm;                                    // S*8*512 floats
    unsigned long long* sA =
        (unsigned long long*)(dsm + (size_t)S * 8 * 512 * 4);   // [19][KC]
    float* sRaw = (float*)(sA + N_NODES * KC);                  // [19][KC] (MODE!=1)
    __shared__ float s_adj[N_NODES * N_NODES];

    const int tid = threadIdx.x;
    const int colbase = blockIdx.x * 512;
    const int kbeg = blockIdx.y * KC;

    constexpr int NST = KC / 8;   // 8-k stages in this slab

    // issue one stage's cp.async loads (16 KB; 8 x 16B per thread)
    auto issue_stage = [&](int s) {
        const float* gsrc = W + (size_t)(kbeg + s * 8) * N + colbase;
        float* dst = sW + (s % S) * 4096;
#pragma unroll
        for (int j = 0; j < 8; ++j) {
            int id  = tid + j * 128;          // 0..1023
            int row = id >> 7;                // 8 rows
            int cp  = (id & 127) << 2;        // 128 x 4-col chunks
            unsigned sm =
                (unsigned)__cvta_generic_to_shared(dst + row * 512 + cp);
            const float* g = gsrc + (size_t)row * N + cp;
            asm volatile("cp.async.cg.shared.global [%0], [%1], 16;\n"
                         :: "r"(sm), "l"(g));
        }
    };

    // start W pipeline BEFORE the A staging work so DRAM latency overlaps it
#pragma unroll
    for (int s = 0; s < S - 1; ++s) {
        if (s < NST) issue_stage(s);
        asm volatile("cp.async.commit_group;\n");
    }

    // lazy zeroing for a future accumulator
    if (zbuf) {
        int n4 = zn >> 2;
        float4 zz = make_float4(0.f, 0.f, 0.f, 0.f);
        for (int q = (blockIdx.y * gridDim.x + blockIdx.x) * 128 + tid;
             q < n4; q += gridDim.x * gridDim.y * 128)
            reinterpret_cast<float4*>(zbuf)[q] = zz;
    }
    if (MODE != 1) {
        for (int i = tid; i < N_NODES * N_NODES; i += 128)
            s_adj[i] = g_adjf[i];
    }

    // ---- stage A slab (fused epilogue/agg), duplicated pairs ----
    for (int i = tid; i < N_NODES * KC; i += 128) {
        int r = i / KC, k = i - r * KC;
        float a = Ain[r * K + kbeg + k];
        if (MODE >= 1) a = fmaxf(a + bias[kbeg + k], 0.0f);
        if (MODE == 1) {
            unsigned long long p;
            asm("mov.b64 %0, {%1, %1};" : "=l"(p) : "f"(a));
            sA[i] = p;
        } else {
            sRaw[i] = a;
        }
    }
    __syncthreads();
    if (MODE != 1) {
        for (int i = tid; i < N_NODES * KC; i += 128) {
            int r = i / KC, k = i - r * KC;
            float a = sRaw[r * KC + k];
#pragma unroll
            for (int s = 0; s < N_NODES; ++s)
                a += s_adj[r * N_NODES + s] * sRaw[s * KC + k];
            unsigned long long p;
            asm("mov.b64 %0, {%1, %1};" : "=l"(p) : "f"(a));
            sA[i] = p;
        }
        __syncthreads();
    }

    // acc0[r] = cols {0,1}, acc1[r] = cols {2,3} (packed f32x2)
    unsigned long long acc0[N_NODES], acc1[N_NODES];
#pragma unroll
    for (int r = 0; r < N_NODES; ++r) { acc0[r] = 0ull; acc1[r] = 0ull; }

#pragma unroll 1
    for (int st = 0; st < NST; ++st) {
        asm volatile("cp.async.wait_group %0;\n" :: "n"(S - 2));
        __syncthreads();   // stage st arrived; buffer (st-1)%S free

        // issue next stage FIRST (into the just-freed buffer), then compute
        if (st + S - 1 < NST) issue_stage(st + S - 1);
        asm volatile("cp.async.commit_group;\n");

        const float* wb = sW + (st % S) * 4096;
        ulonglong2 wv0 = *reinterpret_cast<const ulonglong2*>(wb + 4 * tid);
        ulonglong2 wv1 = *reinterpret_cast<const ulonglong2*>(wb + 512 + 4 * tid);

#pragma unroll
        for (int kk = 0; kk < 8; kk += 2) {
            ulonglong2 nwv0 = wv0, nwv1 = wv1;
            if (kk < 6) {   // hoist next k-pair's W
                nwv0 = *reinterpret_cast<const ulonglong2*>(
                           wb + (kk + 2) * 512 + 4 * tid);
                nwv1 = *reinterpret_cast<const ulonglong2*>(
                           wb + (kk + 3) * 512 + 4 * tid);
            }
            const int koff = st * 8 + kk;
            ulonglong2 cur[4], nxt[4];
#pragma unroll
            for (int j = 0; j < 4; ++j)
                cur[j] = *reinterpret_cast<const ulonglong2*>(
                             sA + j * KC + koff);
#pragma unroll
            for (int b = 0; b < 5; ++b) {
                const int base = b * 4;
#pragma unroll
                for (int j = 0; j < 4; ++j) {
                    const int nr = base + 4 + j;
                    nxt[j] = (nr < N_NODES)
                                 ? *reinterpret_cast<const ulonglong2*>(
                                       sA + nr * KC + koff)
                                 : cur[j];
                }
#pragma unroll
                for (int j = 0; j < 4; ++j) {
                    const int r = base + j;
                    if (r < N_NODES) {
                        asm("fma.rn.f32x2 %0, %1, %2, %0;"
                            : "+l"(acc0[r]) : "l"(cur[j].x), "l"(wv0.x));
                        asm("fma.rn.f32x2 %0, %1, %2, %0;"
                            : "+l"(acc1[r]) : "l"(cur[j].x), "l"(wv0.y));
                        asm("fma.rn.f32x2 %0, %1, %2, %0;"
                            : "+l"(acc0[r]) : "l"(cur[j].y), "l"(wv1.x));
                        asm("fma.rn.f32x2 %0, %1, %2, %0;"
                            : "+l"(acc1[r]) : "l"(cur[j].y), "l"(wv1.y));
                    }
                }
#pragma unroll
                for (int j = 0; j < 4; ++j) cur[j] = nxt[j];
            }
            wv0 = nwv0; wv1 = nwv1;
        }
    }

    // ---- epilogue: one 128-bit reduction per row ----
    const int col = colbase + tid * 4;
#pragma unroll
    for (int r = 0; r < N_NODES; ++r) {
        float2 a01 = *reinterpret_cast<float2*>(&acc0[r]);
        float2 a23 = *reinterpret_cast<float2*>(&acc1[r]);
        asm volatile("red.global.add.v4.f32 [%0], {%1, %2, %3, %4};"
                     :: "l"(Cacc + r * N + col),
                        "f"(a01.x), "f"(a01.y), "f"(a23.x), "f"(a23.y)
                     : "memory");
    }
}

// ---------------- FC1 fused: flat = acc + b2b (also written to out1);
//                  v[512] += flat @ Wc1 --------------------------------------
__global__ __launch_bounds__(128) void fc1_kernel(
        const float* __restrict__ acc, const float* __restrict__ b2b,
        const float* __restrict__ Wc1, float* __restrict__ v,
        float* __restrict__ out1, int rows_per) {
    const int ROWS = N_NODES * N_T;
    int t = threadIdx.x;                       // cols 4t..4t+3
    int r0 = blockIdx.x * rows_per;
    int r1 = min(r0 + rows_per, ROWS);
    float4 s = make_float4(0.f, 0.f, 0.f, 0.f);
    int i = r0;
    for (; i + 8 <= r1; i += 8) {
        float f[8];
        float4 w[8];
#pragma unroll
        for (int u = 0; u < 8; ++u) {
            f[u] = acc[i + u] + b2b[(i + u) & (N_T - 1)];
            w[u] = *reinterpret_cast<const float4*>(
                       &Wc1[(size_t)(i + u) * LATENT + 4 * t]);
        }
#pragma unroll
        for (int u = 0; u < 8; ++u) {
            if (t == ((i + u) & 127)) out1[i + u] = f[u];
            s.x += f[u] * w[u].x; s.y += f[u] * w[u].y;
            s.z += f[u] * w[u].z; s.w += f[u] * w[u].w;
        }
    }
    for (; i < r1; ++i) {
        float f = acc[i] + b2b[i & (N_T - 1)];
        if (t == (i & 127)) out1[i] = f;
        float4 w = *reinterpret_cast<const float4*>(
                       &Wc1[(size_t)i * LATENT + 4 * t]);
        s.x += f * w.x; s.y += f * w.y; s.z += f * w.z; s.w += f * w.w;
    }
    asm volatile("red.global.add.v4.f32 [%0], {%1, %2, %3, %4};"
                 :: "l"(v + 4 * t), "f"(s.x), "f"(s.y), "f"(s.z), "f"(s.w)
                 : "memory");
}

// ---------------- FC2 + sigmoid ---------------------------------------------
__global__ void fc2_kernel(const float* __restrict__ v,
                           const float* __restrict__ bc1,
                           const float* __restrict__ Wc2,
                           const float* __restrict__ bc2,
                           float* __restrict__ out) {
    __shared__ float red[LATENT];
    int j = threadIdx.x;
    red[j] = (v[j] + bc1[j]) * Wc2[j];
    __syncthreads();
    for (int s = LATENT / 2; s > 0; s >>= 1) {
        if (j < s) red[j] += red[j + s];
        __syncthreads();
    }
    if (j == 0) out[0] = 1.0f / (1.0f + expf(-(red[0] + bc2[0])));
}

// ---------------- launch ----------------------------------------------------
#define PIPE_S 3
static inline int pipe_smem(int kc, int mode) {
    return PIPE_S * 8 * 512 * 4 + kc * N_NODES * 8 +
           (mode != 1 ? kc * N_NODES * 4 : 0);
}

extern "C" void kernel_launch(void* const* d_in, const int* in_sizes, int n_in,
                              void* d_out, int out_size) {
    const float* z    = (const float*)d_in[0];
    const void*  eidx = d_in[1];
    const float* W1a  = (const float*)d_in[2];
    const float* b1a  = (const float*)d_in[3];
    const float* W1b  = (const float*)d_in[4];
    const float* b1b  = (const float*)d_in[5];
    const float* W2a  = (const float*)d_in[6];
    const float* b2a  = (const float*)d_in[7];
    const float* W2b  = (const float*)d_in[8];
    const float* b2b  = (const float*)d_in[9];
    const float* Wc1  = (const float*)d_in[10];
    const float* bc1  = (const float*)d_in[11];
    const float* Wc2  = (const float*)d_in[12];
    const float* bc2  = (const float*)d_in[13];
    float* out = (float*)d_out;

    float *accA, *accB, *accC, *v;
    cudaGetSymbolAddress((void**)&accA, g_accA);
    cudaGetSymbolAddress((void**)&accB, g_accB);
    cudaGetSymbolAddress((void**)&accC, g_accC);
    cudaGetSymbolAddress((void**)&v,    g_v);

    const int nNT = N_NODES * N_T;   // 77824

    // opt-in to >48KB dynamic smem (idempotent; host-state only)
    static int attr_done = 0;
    if (!attr_done) {
        cudaFuncSetAttribute(gemm_pipe<32, 0, PIPE_S>,
            cudaFuncAttributeMaxDynamicSharedMemorySize, pipe_smem(32, 0));
        cudaFuncSetAttribute(gemm_pipe<32, 1, PIPE_S>,
            cudaFuncAttributeMaxDynamicSharedMemorySize, pipe_smem(32, 1));
        cudaFuncSetAttribute(gemm_pipe<32, 2, PIPE_S>,
            cudaFuncAttributeMaxDynamicSharedMemorySize, pipe_smem(32, 2));
        cudaFuncSetAttribute(gemm_pipe<64, 1, PIPE_S>,
            cudaFuncAttributeMaxDynamicSharedMemorySize, pipe_smem(64, 1));
        attr_done = 1;
    }

    // K0: adjacency + zero accA/accB/accC/v
    init_kernel<<<148, 256>>>(eidx, accA, accB, accC, v);

    // g1a: accA = agg(z) @ W1a          [19,512]x[512,2048]   64 blocks
    gemm_pipe<32, 0, PIPE_S><<<dim3(HID / 512, LATENT / 32), 128,
                               pipe_smem(32, 0)>>>(
        z, nullptr, W1a, accA, nullptr, 0, LATENT, HID);

    // g1b: accB = relu(accA+b1a) @ W1b  [19,2048]x[2048,2048] 256 blocks
    gemm_pipe<32, 1, PIPE_S><<<dim3(HID / 512, HID / 32), 128,
                               pipe_smem(32, 1)>>>(
        accA, b1a, W1b, accB, nullptr, 0, HID, HID);

    // g2a: accC = agg(relu(accB+b1b)) @ W2a  [19,2048]x[2048,4096] 512 blocks
    //      (also lazily zeroes accA for g2b)
    gemm_pipe<32, 2, PIPE_S><<<dim3(N_T / 512, HID / 32), 128,
                               pipe_smem(32, 2)>>>(
        accB, b1b, W2a, accC, accA, nNT, HID, N_T);

    // g2b: accA = relu(accC+b2a) @ W2b  [19,4096]x[4096,4096] 512 blocks
    gemm_pipe<64, 1, PIPE_S><<<dim3(N_T / 512, N_T / 64), 128,
                               pipe_smem(64, 1)>>>(
        accC, b2a, W2b, accA, nullptr, 0, N_T, N_T);

    // classifier: epilogue (+b2b, write out[1:]) fused into FC1
    fc1_kernel<<<592, 128>>>(accA, b2b, Wc1, v, out + 1, 132);
    fc2_kernel<<<1, 512>>>(v, bc1, Wc2, bc2, out);
}

// round 11
// speedup vs baseline: 1.3036x; 1.0536x over previous
#include <cuda_runtime.h>
#include <cuda_bf16.h>
#include <math.h>

#define N_NODES 19
#define N_T     4096
#define LATENT  512
#define HID     2048
#define N_EDGES 342

// ---------------- scratch (__device__ globals; no allocs allowed) -----------
__device__ __align__(16) float g_accA[N_NODES * N_T];
__device__ __align__(16) float g_accB[N_NODES * N_T];
__device__ __align__(16) float g_accC[N_NODES * N_T];
__device__ __align__(16) float g_v[LATENT];
__device__ float g_adjf[N_NODES * N_NODES]; // dense edge-count matrix [dst][src]

// ---------------- K0: adjacency + zero all accumulators ---------------------
__global__ void init_kernel(const void* __restrict__ eidx,
                            float* __restrict__ accA,
                            float* __restrict__ accB,
                            float* __restrict__ accC,
                            float* __restrict__ v) {
    int t = threadIdx.x;
    if (blockIdx.x == 0) {
        __shared__ int cnt[N_NODES * N_NODES];
        __shared__ int s_i64;
        for (int i = t; i < N_NODES * N_NODES; i += blockDim.x) cnt[i] = 0;
        if (t == 0) {
            const long long* e64 = (const long long*)eidx;
            int ok = 1;
            for (int i = 0; i < N_EDGES; ++i) {
                long long x = e64[i];
                if (x < 0 || x >= N_NODES) { ok = 0; break; }
            }
            s_i64 = ok;
        }
        __syncthreads();
        const long long* e64 = (const long long*)eidx;
        const int*       e32 = (const int*)eidx;
        for (int e = t; e < N_EDGES; e += blockDim.x) {
            int src, dst;
            if (s_i64) { src = (int)e64[e]; dst = (int)e64[N_EDGES + e]; }
            else       { src = e32[e];      dst = e32[N_EDGES + e]; }
            atomicAdd(&cnt[dst * N_NODES + src], 1);
        }
        __syncthreads();
        for (int i = t; i < N_NODES * N_NODES; i += blockDim.x)
            g_adjf[i] = (float)cnt[i];
        for (int i = t; i < LATENT; i += blockDim.x) v[i] = 0.0f;
    }
    const int n4 = (N_NODES * N_T) >> 2;
    float4 zz = make_float4(0.f, 0.f, 0.f, 0.f);
    for (int q = blockIdx.x * blockDim.x + t; q < n4;
         q += gridDim.x * blockDim.x) {
        reinterpret_cast<float4*>(accA)[q] = zz;
        reinterpret_cast<float4*>(accB)[q] = zz;
        reinterpret_cast<float4*>(accC)[q] = zz;
    }
}

// ---------------- fused split-K GEMM, outer-product inner loop --------------
// Cacc += stage(Ain)[19, K] @ W[K, N].  128 threads x 4 cols = 512-col tile.
// W streamed via S-stage cp.async ring (stage = 8 k-rows x 512 cols = 16 KB).
// Inner loop (NEW, R11): the thread's W stage slice (8k x 4cols) is hoisted
// ONCE into 8 ulonglong2 registers; then per A-row: 4 broadcast LDS.128 +
// 16 FFMA2, no register rotation/copies. Rows self-pipeline (row r's loads
// issue while row r-1's FFMA chain drains). ~390 instr/stage vs ~580 before.
// Epilogue: one red.global.add.v4.f32 per row.
// MODE 0: stage = agg(Ain); 1: relu(Ain+bias); 2: agg(relu(Ain+bias)).
template<int KC, int MODE, int S>
__global__ __launch_bounds__(128) void gemm_pipe(
        const float* __restrict__ Ain, const float* __restrict__ bias,
        const float* __restrict__ W, float* __restrict__ Cacc,
        float* __restrict__ zbuf, int zn, int K, int N) {
    extern __shared__ __align__(16) char dsm[];
    float* sW = (float*)dsm;                                    // S*8*512 floats
    unsigned long long* sA =
        (unsigned long long*)(dsm + (size_t)S * 8 * 512 * 4);   // [19][KC]
    float* sRaw = (float*)(sA + N_NODES * KC);                  // [19][KC] (MODE!=1)
    __shared__ float s_adj[N_NODES * N_NODES];

    const int tid = threadIdx.x;
    const int colbase = blockIdx.x * 512;
    const int kbeg = blockIdx.y * KC;

    constexpr int NST = KC / 8;   // 8-k stages in this slab

    // issue one stage's cp.async loads (16 KB; 8 x 16B per thread)
    auto issue_stage = [&](int s) {
        const float* gsrc = W + (size_t)(kbeg + s * 8) * N + colbase;
        float* dst = sW + (s % S) * 4096;
#pragma unroll
        for (int j = 0; j < 8; ++j) {
            int id  = tid + j * 128;          // 0..1023
            int row = id >> 7;                // 8 rows
            int cp  = (id & 127) << 2;        // 128 x 4-col chunks
            unsigned sm =
                (unsigned)__cvta_generic_to_shared(dst + row * 512 + cp);
            const float* g = gsrc + (size_t)row * N + cp;
            asm volatile("cp.async.cg.shared.global [%0], [%1], 16;\n"
                         :: "r"(sm), "l"(g));
        }
    };

    // start W pipeline BEFORE the A staging work so DRAM latency overlaps it
#pragma unroll
    for (int s = 0; s < S - 1; ++s) {
        if (s < NST) issue_stage(s);
        asm volatile("cp.async.commit_group;\n");
    }

    // lazy zeroing for a future accumulator
    if (zbuf) {
        int n4 = zn >> 2;
        float4 zz = make_float4(0.f, 0.f, 0.f, 0.f);
        for (int q = (blockIdx.y * gridDim.x + blockIdx.x) * 128 + tid;
             q < n4; q += gridDim.x * gridDim.y * 128)
            reinterpret_cast<float4*>(zbuf)[q] = zz;
    }
    if (MODE != 1) {
        for (int i = tid; i < N_NODES * N_NODES; i += 128)
            s_adj[i] = g_adjf[i];
    }

    // ---- stage A slab (fused epilogue/agg), duplicated pairs ----
    for (int i = tid; i < N_NODES * KC; i += 128) {
        int r = i / KC, k = i - r * KC;
        float a = Ain[r * K + kbeg + k];
        if (MODE >= 1) a = fmaxf(a + bias[kbeg + k], 0.0f);
        if (MODE == 1) {
            unsigned long long p;
            asm("mov.b64 %0, {%1, %1};" : "=l"(p) : "f"(a));
            sA[i] = p;
        } else {
            sRaw[i] = a;
        }
    }
    __syncthreads();
    if (MODE != 1) {
        for (int i = tid; i < N_NODES * KC; i += 128) {
            int r = i / KC, k = i - r * KC;
            float a = sRaw[r * KC + k];
#pragma unroll
            for (int s = 0; s < N_NODES; ++s)
                a += s_adj[r * N_NODES + s] * sRaw[s * KC + k];
            unsigned long long p;
            asm("mov.b64 %0, {%1, %1};" : "=l"(p) : "f"(a));
            sA[i] = p;
        }
        __syncthreads();
    }

    // acc0[r] = cols {0,1}, acc1[r] = cols {2,3} (packed f32x2)
    unsigned long long acc0[N_NODES], acc1[N_NODES];
#pragma unroll
    for (int r = 0; r < N_NODES; ++r) { acc0[r] = 0ull; acc1[r] = 0ull; }

#pragma unroll 1
    for (int st = 0; st < NST; ++st) {
        asm volatile("cp.async.wait_group %0;\n" :: "n"(S - 2));
        __syncthreads();   // stage st arrived; buffer (st-1)%S free

        // issue next stage FIRST (into the just-freed buffer), then compute
        if (st + S - 1 < NST) issue_stage(st + S - 1);
        asm volatile("cp.async.commit_group;\n");

        // hoist this thread's entire W stage slice: 8 k x 4 cols
        const float* wb = sW + (st % S) * 4096;
        ulonglong2 wr[8];
#pragma unroll
        for (int j = 0; j < 8; ++j)
            wr[j] = *reinterpret_cast<const ulonglong2*>(
                        wb + j * 512 + 4 * tid);

        // outer-product over rows: 4 broadcast LDS.128 + 16 FFMA2 per row
        const unsigned long long* ab = sA + st * 8;
#pragma unroll
        for (int r = 0; r < N_NODES; ++r) {
            ulonglong2 a0 = *reinterpret_cast<const ulonglong2*>(ab + r * KC);
            ulonglong2 a1 = *reinterpret_cast<const ulonglong2*>(ab + r * KC + 2);
            ulonglong2 a2 = *reinterpret_cast<const ulonglong2*>(ab + r * KC + 4);
            ulonglong2 a3 = *reinterpret_cast<const ulonglong2*>(ab + r * KC + 6);
#define FF(ap, wk)                                                     \
            asm("fma.rn.f32x2 %0, %1, %2, %0;"                          \
                : "+l"(acc0[r]) : "l"(ap), "l"(wr[wk].x));              \
            asm("fma.rn.f32x2 %0, %1, %2, %0;"                          \
                : "+l"(acc1[r]) : "l"(ap), "l"(wr[wk].y));
            FF(a0.x, 0) FF(a0.y, 1) FF(a1.x, 2) FF(a1.y, 3)
            FF(a2.x, 4) FF(a2.y, 5) FF(a3.x, 6) FF(a3.y, 7)
#undef FF
        }
    }

    // ---- epilogue: one 128-bit reduction per row ----
    const int col = colbase + tid * 4;
#pragma unroll
    for (int r = 0; r < N_NODES; ++r) {
        float2 a01 = *reinterpret_cast<float2*>(&acc0[r]);
        float2 a23 = *reinterpret_cast<float2*>(&acc1[r]);
        asm volatile("red.global.add.v4.f32 [%0], {%1, %2, %3, %4};"
                     :: "l"(Cacc + r * N + col),
                        "f"(a01.x), "f"(a01.y), "f"(a23.x), "f"(a23.y)
                     : "memory");
    }
}

// ---------------- FC1 fused: flat = acc + b2b (also written to out1);
//                  v[512] += flat @ Wc1 --------------------------------------
__global__ __launch_bounds__(128) void fc1_kernel(
        const float* __restrict__ acc, const float* __restrict__ b2b,
        const float* __restrict__ Wc1, float* __restrict__ v,
        float* __restrict__ out1, int rows_per) {
    const int ROWS = N_NODES * N_T;
    int t = threadIdx.x;                       // cols 4t..4t+3
    int r0 = blockIdx.x * rows_per;
    int r1 = min(r0 + rows_per, ROWS);
    float4 s = make_float4(0.f, 0.f, 0.f, 0.f);
    int i = r0;
    for (; i + 8 <= r1; i += 8) {
        float f[8];
        float4 w[8];
#pragma unroll
        for (int u = 0; u < 8; ++u) {
            f[u] = acc[i + u] + b2b[(i + u) & (N_T - 1)];
            w[u] = *reinterpret_cast<const float4*>(
                       &Wc1[(size_t)(i + u) * LATENT + 4 * t]);
        }
#pragma unroll
        for (int u = 0; u < 8; ++u) {
            if (t == ((i + u) & 127)) out1[i + u] = f[u];
            s.x += f[u] * w[u].x; s.y += f[u] * w[u].y;
            s.z += f[u] * w[u].z; s.w += f[u] * w[u].w;
        }
    }
    for (; i < r1; ++i) {
        float f = acc[i] + b2b[i & (N_T - 1)];
        if (t == (i & 127)) out1[i] = f;
        float4 w = *reinterpret_cast<const float4*>(
                       &Wc1[(size_t)i * LATENT + 4 * t]);
        s.x += f * w.x; s.y += f * w.y; s.z += f * w.z; s.w += f * w.w;
    }
    asm volatile("red.global.add.v4.f32 [%0], {%1, %2, %3, %4};"
                 :: "l"(v + 4 * t), "f"(s.x), "f"(s.y), "f"(s.z), "f"(s.w)
                 : "memory");
}

// ---------------- FC2 + sigmoid ---------------------------------------------
__global__ void fc2_kernel(const float* __restrict__ v,
                           const float* __restrict__ bc1,
                           const float* __restrict__ Wc2,
                           const float* __restrict__ bc2,
                           float* __restrict__ out) {
    __shared__ float red[LATENT];
    int j = threadIdx.x;
    red[j] = (v[j] + bc1[j]) * Wc2[j];
    __syncthreads();
    for (int s = LATENT / 2; s > 0; s >>= 1) {
        if (j < s) red[j] += red[j + s];
        __syncthreads();
    }
    if (j == 0) out[0] = 1.0f / (1.0f + expf(-(red[0] + bc2[0])));
}

// ---------------- launch ----------------------------------------------------
#define PIPE_S 3
static inline int pipe_smem(int kc, int mode) {
    return PIPE_S * 8 * 512 * 4 + kc * N_NODES * 8 +
           (mode != 1 ? kc * N_NODES * 4 : 0);
}

extern "C" void kernel_launch(void* const* d_in, const int* in_sizes, int n_in,
                              void* d_out, int out_size) {
    const float* z    = (const float*)d_in[0];
    const void*  eidx = d_in[1];
    const float* W1a  = (const float*)d_in[2];
    const float* b1a  = (const float*)d_in[3];
    const float* W1b  = (const float*)d_in[4];
    const float* b1b  = (const float*)d_in[5];
    const float* W2a  = (const float*)d_in[6];
    const float* b2a  = (const float*)d_in[7];
    const float* W2b  = (const float*)d_in[8];
    const float* b2b  = (const float*)d_in[9];
    const float* Wc1  = (const float*)d_in[10];
    const float* bc1  = (const float*)d_in[11];
    const float* Wc2  = (const float*)d_in[12];
    const float* bc2  = (const float*)d_in[13];
    float* out = (float*)d_out;

    float *accA, *accB, *accC, *v;
    cudaGetSymbolAddress((void**)&accA, g_accA);
    cudaGetSymbolAddress((void**)&accB, g_accB);
    cudaGetSymbolAddress((void**)&accC, g_accC);
    cudaGetSymbolAddress((void**)&v,    g_v);

    const int nNT = N_NODES * N_T;   // 77824

    // opt-in to >48KB dynamic smem (idempotent; host-state only)
    static int attr_done = 0;
    if (!attr_done) {
        cudaFuncSetAttribute(gemm_pipe<32, 0, PIPE_S>,
            cudaFuncAttributeMaxDynamicSharedMemorySize, pipe_smem(32, 0));
        cudaFuncSetAttribute(gemm_pipe<32, 1, PIPE_S>,
            cudaFuncAttributeMaxDynamicSharedMemorySize, pipe_smem(32, 1));
        cudaFuncSetAttribute(gemm_pipe<32, 2, PIPE_S>,
            cudaFuncAttributeMaxDynamicSharedMemorySize, pipe_smem(32, 2));
        cudaFuncSetAttribute(gemm_pipe<64, 1, PIPE_S>,
            cudaFuncAttributeMaxDynamicSharedMemorySize, pipe_smem(64, 1));
        attr_done = 1;
    }

    // K0: adjacency + zero accA/accB/accC/v
    init_kernel<<<148, 256>>>(eidx, accA, accB, accC, v);

    // g1a: accA = agg(z) @ W1a          [19,512]x[512,2048]   64 blocks
    gemm_pipe<32, 0, PIPE_S><<<dim3(HID / 512, LATENT / 32), 128,
                               pipe_smem(32, 0)>>>(
        z, nullptr, W1a, accA, nullptr, 0, LATENT, HID);

    // g1b: accB = relu(accA+b1a) @ W1b  [19,2048]x[2048,2048] 256 blocks
    gemm_pipe<32, 1, PIPE_S><<<dim3(HID / 512, HID / 32), 128,
                               pipe_smem(32, 1)>>>(
        accA, b1a, W1b, accB, nullptr, 0, HID, HID);

    // g2a: accC = agg(relu(accB+b1b)) @ W2a  [19,2048]x[2048,4096] 512 blocks
    //      (also lazily zeroes accA for g2b)
    gemm_pipe<32, 2, PIPE_S><<<dim3(N_T / 512, HID / 32), 128,
                               pipe_smem(32, 2)>>>(
        accB, b1b, W2a, accC, accA, nNT, HID, N_T);

    // g2b: accA = relu(accC+b2a) @ W2b  [19,4096]x[4096,4096] 512 blocks
    gemm_pipe<64, 1, PIPE_S><<<dim3(N_T / 512, N_T / 64), 128,
                               pipe_smem(64, 1)>>>(
        accC, b2a, W2b, accA, nullptr, 0, N_T, N_T);

    // classifier: epilogue (+b2b, write out[1:]) fused into FC1
    fc1_kernel<<<1184, 128>>>(accA, b2b, Wc1, v, out + 1, 66);
    fc2_kernel<<<1, 512>>>(v, bc1, Wc2, bc2, out);
}